// round 15
// baseline (speedup 1.0000x reference)
#include <cuda_runtime.h>
#include <math.h>

#define NB 16
#define NS 48
#define SEGLEN 20000
#define ND 256
#define NPIX 65536
#define NVW 512           // 16384 ver bits / 32
#define SIDX 3
#define EIDX 38
#define NSEG (EIDX - SIDX)   // 35
#define K1 8                 // phase-1 segments
#define NITER 34
#define FLAT (NS*ND)
#define NFB (16*NB)          // k_final blocks
#define HT 384               // hist block size: 5 blocks/SM -> 740 slots, ~1 wave

typedef unsigned long long ull;

// ---- scratch (device globals; no allocations) ----
__device__ unsigned g_histX[NB*NS*ND];
__device__ unsigned g_histY[NB*NS*ND];
__device__ float    g_m[2*NB*NS];          // centroids [axis][b][s]
__device__ int      g_al[2*NB*NS];         // aligned shifts [axis][b][s]
__device__ unsigned g_verseg[NB*K1*NVW];   // phase-1 ver bitmaps
__device__ unsigned char g_commit[NB*NS];
__device__ int      g_container[NB*NPIX];
__device__ ull      g_acc[NB][2];          // per-batch s1,s2 exact sums
__device__ unsigned g_fcount;              // k_final completion counter

// ================= hist: full segment per block, MLP=4, 384 threads =================
__global__ void k_hist(const float* __restrict__ ev){
    int s = blockIdx.x, b = blockIdx.y, t = threadIdx.x;   // HT threads

    __shared__ unsigned hx[ND][4], hy[ND][4];
    for(int i = t; i < ND*4; i += HT){
        ((unsigned*)hx)[i] = 0;
        ((unsigned*)hy)[i] = 0;
    }
    __syncthreads();

    const float4* p4 = reinterpret_cast<const float4*>(
        ev + 2*((size_t)b*(NS*SEGLEN) + (size_t)s*SEGLEN));
    int rep = t & 3;
    const int Q = SEGLEN/8;   // 2500 f4 per quarter (10000 f4 total)
    for(int i = t; i < Q; i += HT){
        float4 e0 = p4[i];
        float4 e1 = p4[i + Q];
        float4 e2 = p4[i + 2*Q];
        float4 e3 = p4[i + 3*Q];
        atomicAdd(&hx[(int)e0.x][rep], 1u); atomicAdd(&hy[(int)e0.y][rep], 1u);
        atomicAdd(&hx[(int)e0.z][rep], 1u); atomicAdd(&hy[(int)e0.w][rep], 1u);
        atomicAdd(&hx[(int)e1.x][rep], 1u); atomicAdd(&hy[(int)e1.y][rep], 1u);
        atomicAdd(&hx[(int)e1.z][rep], 1u); atomicAdd(&hy[(int)e1.w][rep], 1u);
        atomicAdd(&hx[(int)e2.x][rep], 1u); atomicAdd(&hy[(int)e2.y][rep], 1u);
        atomicAdd(&hx[(int)e2.z][rep], 1u); atomicAdd(&hy[(int)e2.w][rep], 1u);
        atomicAdd(&hx[(int)e3.x][rep], 1u); atomicAdd(&hy[(int)e3.y][rep], 1u);
        atomicAdd(&hx[(int)e3.z][rep], 1u); atomicAdd(&hy[(int)e3.w][rep], 1u);
    }
    __syncthreads();
    if(t < ND){
        g_histX[(b*NS+s)*ND + t] = hx[t][0] + hx[t][1] + hx[t][2] + hx[t][3];
        g_histY[(b*NS+s)*ND + t] = hy[t][0] + hy[t][1] + hy[t][2] + hy[t][3];
    }
}

// ============ stats: cv + separable blur/centroid -> g_m, g_al ============
__global__ void k_stats(){
    int b = blockIdx.x, ax = blockIdx.y, t = threadIdx.x;   // 512 threads
    __shared__ ull a1[512], a2[512];
    __shared__ double R[NS];
    __shared__ float cvs;
    __shared__ float mloc[NS];

    if(b == 0 && ax == 0 && t == 0) g_fcount = 0;
    if(b == 0 && ax == 0 && t < NB*2) ((ull*)g_acc)[t] = 0;

    const unsigned* h = (ax ? g_histY : g_histX) + b*FLAT;

    ull s1 = 0, s2 = 0;
    for(int i = t; i < FLAT; i += 512){
        unsigned v = h[i];
        s1 += v; s2 += (ull)v*v;
    }
    a1[t] = s1; a2[t] = s2; __syncthreads();
    for(int o = 256; o; o >>= 1){
        if(t < o){ a1[t] += a1[t+o]; a2[t] += a2[t+o]; }
        __syncthreads();
    }
    if(t == 0){
        double n = (double)FLAT;
        double mean = (double)a1[0] / n;
        double var  = ((double)a2[0] - (double)a1[0]*(double)a1[0]/n) / (n - 1.0);
        cvs = (float)(mean + 3.0*sqrt(var));
    }
    __syncthreads();
    float cv = cvs;

    int w = t >> 5, lane = t & 31;
    for(int r = w; r < NS; r += 16){
        const unsigned* row = h + r*ND;
        double acc = 0.0;
        for(int d = lane; d < ND; d += 32){
            float v = fminf((float)row[d], cv);
            acc += (double)v * (double)d;
        }
        #pragma unroll
        for(int o = 16; o; o >>= 1)
            acc += __shfl_down_sync(0xffffffffu, acc, o);
        if(lane == 0){
            double e0   = (double)fminf((float)row[0],   cv);
            double e1   = (double)fminf((float)row[1],   cv);
            double e254 = (double)fminf((float)row[254], cv);
            double e255 = (double)fminf((float)row[255], cv);
            R[r] = 5.0*acc + 3.0*e0 + e1 - 256.0*e254 - 513.0*e255;
        }
    }
    __syncthreads();
    if(t < NS){
        double s = 0.0;
        int lo = t-2 < 0 ? 0 : t-2, hi = t+2 > NS-1 ? NS-1 : t+2;
        for(int i = lo; i <= hi; i++) s += R[i];
        mloc[t] = (float)((0.04 * s) / (double)SEGLEN);
        g_m[ax*NB*NS + b*NS + t] = mloc[t];
    }
    __syncthreads();
    if(t < NS){
        float st = mloc[SIDX];
        float al = rintf((mloc[t] - st) - (128.0f - st));   // exact ref op order
        g_al[ax*NB*NS + b*NS + t] = (int)al;
    }
}

// ========== phase-1 bitmaps (j < K1) + container zeroing ==========
__global__ void k_bitmap1(const float* __restrict__ ev){
    int j = blockIdx.x, b = blockIdx.y, t = threadIdx.x;   // 512 threads
    {
        int base = (b*K1 + j) * 8192;
        int4 z = make_int4(0,0,0,0);
        int4* dst = (int4*)(g_container + base);
        for(int i = t; i < 2048; i += 512) dst[i] = z;
    }
    int si = SIDX + j;
    __shared__ unsigned vbm[NVW];
    vbm[t] = 0;
    __syncthreads();
    int ax = g_al[b*NS + si], ay = g_al[NB*NS + b*NS + si];
    const float4* p = reinterpret_cast<const float4*>(
        ev + 2*((size_t)b*(NS*SEGLEN) + (size_t)si*SEGLEN));
    for(int i = t; i < SEGLEN/4; i += 512){
        float4 e0 = p[i];
        float4 e1 = p[i + SEGLEN/4];
        #define VBIT(px, py) { \
            int xs = min(max((int)(px) - ax, 0), 255); \
            int ys = min(max((int)(py) - ay, 0), 255); \
            int iv = (xs >> 1) + ((ys >> 1) << 7); \
            atomicOr(&vbm[iv >> 5], 1u << (iv & 31)); }
        VBIT(e0.x, e0.y) VBIT(e0.z, e0.w)
        VBIT(e1.x, e1.y) VBIT(e1.z, e1.w)
        #undef VBIT
    }
    __syncthreads();
    g_verseg[(size_t)(b*K1 + j)*NVW + t] = vbm[t];
}

// ---- branchless 10-element sort: optimal 29-comparator network ----
#define CSWAP(i,j) { float lo = fminf(v[i], v[j]); float hi = fmaxf(v[i], v[j]); v[i] = lo; v[j] = hi; }
__device__ __forceinline__ void sort10(float* v){
    CSWAP(0,5) CSWAP(1,6) CSWAP(2,7) CSWAP(3,8) CSWAP(4,9)
    CSWAP(0,3) CSWAP(5,8) CSWAP(1,4) CSWAP(6,9)
    CSWAP(0,2) CSWAP(3,6) CSWAP(7,9)
    CSWAP(0,1) CSWAP(2,4) CSWAP(5,7) CSWAP(8,9)
    CSWAP(1,2) CSWAP(3,5) CSWAP(4,6) CSWAP(7,8)
    CSWAP(1,3) CSWAP(2,5) CSWAP(4,7) CSWAP(6,8)
    CSWAP(2,3) CSWAP(4,5) CSWAP(6,7)
    CSWAP(3,4) CSWAP(5,6)
}
#undef CSWAP

// ========== scan: phase-1 from smem stage; phase-2 on demand from events ==========
__global__ void k_scan(const float* __restrict__ ev){
    int b = blockIdx.x, t = threadIdx.x;   // 512 threads == NVW
    int w = t >> 5, lane = t & 31;
    __shared__ unsigned sver[K1][NVW];     // 16KB: phase-1 bitmaps (sver[0] reused as scratch later)
    __shared__ unsigned redbuf[16];
    __shared__ unsigned s_tot;
    __shared__ float mm[2][NS];
    __shared__ unsigned char sout[NITER];
    __shared__ int s_done;

    if(t < NS) g_commit[b*NS + t] = 0;
    if(t < 2*NS) ((float*)mm)[t] = g_m[(t/NS)*NB*NS + b*NS + (t%NS)];
    {
        const unsigned* src = g_verseg + (size_t)b*K1*NVW;
        #pragma unroll
        for(int j = 0; j < K1; j++) sver[j][t] = src[j*NVW + t];
    }
    if(t == 0) s_done = 0;
    __syncthreads();

    if(t < NITER){
        bool f = false;
        #pragma unroll
        for(int ax = 0; ax < 2; ax++){
            float w10[10], v[10];
            #pragma unroll
            for(int i = 0; i < 10; i++){ w10[i] = mm[ax][SIDX + 1 + t + i]; v[i] = w10[i]; }
            sort10(v);
            float med = 0.5f*(v[4] + v[5]);
            float d0 = fabsf(w10[0] - med);
            #pragma unroll
            for(int i = 0; i < 10; i++) v[i] = fabsf(w10[i] - med);
            sort10(v);
            float mad = 0.5f*(v[4] + v[5]);
            bool fl = (mad == 0.0f) ? (d0 > 0.0f)
                                    : (__fdiv_rn(0.6745f*d0, mad) > 2.0f);
            f = f || fl;
        }
        sout[t] = f ? 1 : 0;
    }
    __syncthreads();

    unsigned va = sver[0][t];
    unsigned nb = __popc(va);
    #pragma unroll
    for(int o = 16; o; o >>= 1) nb += __shfl_down_sync(0xffffffffu, nb, o);
    if(lane == 0) redbuf[w] = nb;
    __syncthreads();
    if(t == 0){
        unsigned s = 0;
        for(int i = 0; i < 16; i++) s += redbuf[i];
        s_tot = s;
    }
    __syncthreads();
    unsigned cnt = s_tot;
    if(t == 0) g_commit[b*NS + SIDX] = 1;

    // ---- phase 1: smem-staged bitmaps ----
    for(int si = SIDX + 1; si < SIDX + K1; ++si){
        if(sout[si - SIDX - 1]) continue;     // outlier: skip, don't stop
        unsigned wv = sver[si - SIDX][t];
        unsigned nw = __popc(wv & ~va);
        #pragma unroll
        for(int o = 16; o; o >>= 1) nw += __shfl_down_sync(0xffffffffu, nw, o);
        if(lane == 0) redbuf[w] = nw;
        __syncthreads();
        if(t == 0){
            unsigned s = 0;
            for(int i = 0; i < 16; i++) s += redbuf[i];
            s_tot = s;
        }
        __syncthreads();
        unsigned ni = s_tot;
        unsigned cn = cnt + ni;
        if(__fdiv_rn((float)ni, (float)cn) < 0.1f){    // stopped forever
            if(t == 0) s_done = 1;
            break;
        }
        va |= wv;
        cnt = cn;
        if(t == 0) g_commit[b*NS + si] = 1;
        __syncthreads();
    }
    __syncthreads();

    // ---- phase 2 (rare): build remaining bitmaps on demand ----
    if(!s_done){
        const float4* base4 = reinterpret_cast<const float4*>(ev + 2*(size_t)b*(NS*SEGLEN));
        for(int si = SIDX + K1; si < EIDX; ++si){
            if(sout[si - SIDX - 1]) continue;
            sver[0][t] = 0;
            __syncthreads();
            int ax = g_al[b*NS + si], ay = g_al[NB*NS + b*NS + si];
            const float4* p = base4 + (size_t)si*(SEGLEN/2);
            for(int i = t; i < SEGLEN/4; i += 512){
                float4 e0 = p[i];
                float4 e1 = p[i + SEGLEN/4];
                #define VBIT(px, py) { \
                    int xs = min(max((int)(px) - ax, 0), 255); \
                    int ys = min(max((int)(py) - ay, 0), 255); \
                    int iv = (xs >> 1) + ((ys >> 1) << 7); \
                    atomicOr(&sver[0][iv >> 5], 1u << (iv & 31)); }
                VBIT(e0.x, e0.y) VBIT(e0.z, e0.w)
                VBIT(e1.x, e1.y) VBIT(e1.z, e1.w)
                #undef VBIT
            }
            __syncthreads();
            unsigned wv = sver[0][t];
            unsigned nw = __popc(wv & ~va);
            #pragma unroll
            for(int o = 16; o; o >>= 1) nw += __shfl_down_sync(0xffffffffu, nw, o);
            if(lane == 0) redbuf[w] = nw;
            __syncthreads();
            if(t == 0){
                unsigned s = 0;
                for(int i = 0; i < 16; i++) s += redbuf[i];
                s_tot = s;
            }
            __syncthreads();
            unsigned ni = s_tot;
            unsigned cn = cnt + ni;
            if(__fdiv_rn((float)ni, (float)cn) < 0.1f) break;
            va |= wv;
            cnt = cn;
            if(t == 0) g_commit[b*NS + si] = 1;
            __syncthreads();
        }
    }
}

// ================= container scatter for committed segments =================
__global__ void k_scatter(const float* __restrict__ ev){
    int si = SIDX + blockIdx.x, b = blockIdx.y, ck = blockIdx.z;   // z: 8 chunks
    if(!g_commit[b*NS + si]) return;
    int ax = g_al[b*NS + si], ay = g_al[NB*NS + b*NS + si];
    const float4* p = reinterpret_cast<const float4*>(
        ev + 2*((size_t)b*(NS*SEGLEN) + (size_t)si*SEGLEN));
    int* cont = g_container + b*NPIX;
    int lo = ck * (SEGLEN/16), hi = lo + (SEGLEN/16);
    for(int i = lo + threadIdx.x; i < hi; i += blockDim.x){
        float4 e = p[i];
        {
            int xs = min(max((int)e.x - ax, 0), 255);
            int ys = min(max((int)e.y - ay, 0), 255);
            atomicAdd(&cont[xs + (ys << 8)], 1);
        }
        {
            int xs = min(max((int)e.z - ax, 0), 255);
            int ys = min(max((int)e.w - ay, 0), 255);
            atomicAdd(&cont[xs + (ys << 8)], 1);
        }
    }
}

// ========== final: single-pass stats + normalize (device-side sync) ==========
// grid (16, NB) = 256 blocks, all co-resident (256 < 592 slots) -> spin is safe
__global__ void k_final(float* __restrict__ out){
    int pb = blockIdx.x, b = blockIdx.y, t = threadIdx.x;   // 512 threads
    const int* c = g_container + b*NPIX + pb*4096;
    int vals[8];
    ull s1 = 0, s2 = 0;
    #pragma unroll
    for(int k = 0; k < 8; k++){
        int v = c[t + 512*k];
        vals[k] = v;
        s1 += (unsigned)v;
        s2 += (ull)(unsigned)v * (unsigned)v;
    }
    __shared__ ull a1[512], a2[512];
    __shared__ float scv;
    a1[t] = s1; a2[t] = s2; __syncthreads();
    for(int o = 256; o; o >>= 1){
        if(t < o){ a1[t] += a1[t+o]; a2[t] += a2[t+o]; }
        __syncthreads();
    }
    if(t == 0){
        atomicAdd(&g_acc[b][0], a1[0]);
        atomicAdd(&g_acc[b][1], a2[0]);
        __threadfence();
        unsigned done = atomicAdd(&g_fcount, 1u) + 1;
        while(done < NFB){
            __nanosleep(64);
            done = atomicAdd(&g_fcount, 0u);
        }
        __threadfence();
        double n = (double)NPIX;
        double t1 = (double)atomicAdd(&g_acc[b][0], 0ULL);
        double t2 = (double)atomicAdd(&g_acc[b][1], 0ULL);
        double mean = t1 / n;
        double var  = (t2 - t1*t1/n) / (n - 1.0);
        scv = (float)(mean + 3.0*sqrt(var));
    }
    __syncthreads();
    float cv = scv;
    float* o = out + b*NPIX + pb*4096;
    #pragma unroll
    for(int k = 0; k < 8; k++){
        float v = fminf((float)vals[k], cv);
        o[t + 512*k] = __fdiv_rn(v, cv);
    }
}

// ================= launch =================
extern "C" void kernel_launch(void* const* d_in, const int* in_sizes, int n_in,
                              void* d_out, int out_size){
    const float* ev = (const float*)d_in[0];
    float* out = (float*)d_out;
    (void)in_sizes; (void)n_in; (void)out_size;

    { dim3 g(NS, NB);      k_hist   <<<g, HT>>>(ev); }
    { dim3 g(NB, 2);       k_stats  <<<g, 512>>>(); }
    { dim3 g(K1, NB);      k_bitmap1<<<g, 512>>>(ev); }
    k_scan<<<NB, NVW>>>(ev);                              // profile slot #4 (canary)
    { dim3 g(NSEG, NB, 8); k_scatter<<<g, 512>>>(ev); }
    { dim3 g(16, NB);      k_final  <<<g, 512>>>(out); }
}

// round 16
// speedup vs baseline: 1.0636x; 1.0636x over previous
#include <cuda_runtime.h>
#include <math.h>

#define NB 16
#define NS 48
#define SEGLEN 20000
#define ND 256
#define NPIX 65536
#define NVW 512           // 16384 ver bits / 32
#define SIDX 3
#define EIDX 38
#define NSEG (EIDX - SIDX)   // 35
#define K1 12                // phase-1 segments (covers late-break batches)
#define NITER 34
#define FLAT (NS*ND)
#define NFB (16*NB)          // k_final blocks
#define HT 384               // hist block size

typedef unsigned long long ull;

// ---- scratch (device globals; no allocations) ----
__device__ unsigned g_histX[NB*NS*ND];
__device__ unsigned g_histY[NB*NS*ND];
__device__ float    g_m[2*NB*NS];          // centroids [axis][b][s]
__device__ int      g_al[2*NB*NS];         // aligned shifts [axis][b][s]
__device__ unsigned g_verseg[NB*K1*NVW];   // phase-1 ver bitmaps
__device__ unsigned char g_commit[NB*NS];
__device__ int      g_container[NB*NPIX];
__device__ ull      g_acc[NB][2];          // per-batch s1,s2 exact sums
__device__ unsigned g_fcount;              // k_final completion counter

// ================= hist: full segment per block, MLP=4 =================
__global__ void k_hist(const float* __restrict__ ev){
    int s = blockIdx.x, b = blockIdx.y, t = threadIdx.x;   // HT threads

    __shared__ unsigned hx[ND][4], hy[ND][4];
    for(int i = t; i < ND*4; i += HT){
        ((unsigned*)hx)[i] = 0;
        ((unsigned*)hy)[i] = 0;
    }
    __syncthreads();

    const float4* p4 = reinterpret_cast<const float4*>(
        ev + 2*((size_t)b*(NS*SEGLEN) + (size_t)s*SEGLEN));
    int rep = t & 3;
    const int Q = SEGLEN/8;   // 2500 f4 per quarter (10000 f4 total)
    for(int i = t; i < Q; i += HT){
        float4 e0 = p4[i];
        float4 e1 = p4[i + Q];
        float4 e2 = p4[i + 2*Q];
        float4 e3 = p4[i + 3*Q];
        atomicAdd(&hx[(int)e0.x][rep], 1u); atomicAdd(&hy[(int)e0.y][rep], 1u);
        atomicAdd(&hx[(int)e0.z][rep], 1u); atomicAdd(&hy[(int)e0.w][rep], 1u);
        atomicAdd(&hx[(int)e1.x][rep], 1u); atomicAdd(&hy[(int)e1.y][rep], 1u);
        atomicAdd(&hx[(int)e1.z][rep], 1u); atomicAdd(&hy[(int)e1.w][rep], 1u);
        atomicAdd(&hx[(int)e2.x][rep], 1u); atomicAdd(&hy[(int)e2.y][rep], 1u);
        atomicAdd(&hx[(int)e2.z][rep], 1u); atomicAdd(&hy[(int)e2.w][rep], 1u);
        atomicAdd(&hx[(int)e3.x][rep], 1u); atomicAdd(&hy[(int)e3.y][rep], 1u);
        atomicAdd(&hx[(int)e3.z][rep], 1u); atomicAdd(&hy[(int)e3.w][rep], 1u);
    }
    __syncthreads();
    if(t < ND){
        g_histX[(b*NS+s)*ND + t] = hx[t][0] + hx[t][1] + hx[t][2] + hx[t][3];
        g_histY[(b*NS+s)*ND + t] = hy[t][0] + hy[t][1] + hy[t][2] + hy[t][3];
    }
}

// ============ stats: cv + separable blur/centroid -> g_m, g_al ============
__global__ void k_stats(){
    int b = blockIdx.x, ax = blockIdx.y, t = threadIdx.x;   // 512 threads
    __shared__ ull a1[512], a2[512];
    __shared__ double R[NS];
    __shared__ float cvs;
    __shared__ float mloc[NS];

    if(b == 0 && ax == 0 && t == 0) g_fcount = 0;
    if(b == 0 && ax == 0 && t < NB*2) ((ull*)g_acc)[t] = 0;

    const unsigned* h = (ax ? g_histY : g_histX) + b*FLAT;

    ull s1 = 0, s2 = 0;
    for(int i = t; i < FLAT; i += 512){
        unsigned v = h[i];
        s1 += v; s2 += (ull)v*v;
    }
    a1[t] = s1; a2[t] = s2; __syncthreads();
    for(int o = 256; o; o >>= 1){
        if(t < o){ a1[t] += a1[t+o]; a2[t] += a2[t+o]; }
        __syncthreads();
    }
    if(t == 0){
        double n = (double)FLAT;
        double mean = (double)a1[0] / n;
        double var  = ((double)a2[0] - (double)a1[0]*(double)a1[0]/n) / (n - 1.0);
        cvs = (float)(mean + 3.0*sqrt(var));
    }
    __syncthreads();
    float cv = cvs;

    int w = t >> 5, lane = t & 31;
    for(int r = w; r < NS; r += 16){
        const unsigned* row = h + r*ND;
        double acc = 0.0;
        for(int d = lane; d < ND; d += 32){
            float v = fminf((float)row[d], cv);
            acc += (double)v * (double)d;
        }
        #pragma unroll
        for(int o = 16; o; o >>= 1)
            acc += __shfl_down_sync(0xffffffffu, acc, o);
        if(lane == 0){
            double e0   = (double)fminf((float)row[0],   cv);
            double e1   = (double)fminf((float)row[1],   cv);
            double e254 = (double)fminf((float)row[254], cv);
            double e255 = (double)fminf((float)row[255], cv);
            R[r] = 5.0*acc + 3.0*e0 + e1 - 256.0*e254 - 513.0*e255;
        }
    }
    __syncthreads();
    if(t < NS){
        double s = 0.0;
        int lo = t-2 < 0 ? 0 : t-2, hi = t+2 > NS-1 ? NS-1 : t+2;
        for(int i = lo; i <= hi; i++) s += R[i];
        mloc[t] = (float)((0.04 * s) / (double)SEGLEN);
        g_m[ax*NB*NS + b*NS + t] = mloc[t];
    }
    __syncthreads();
    if(t < NS){
        float st = mloc[SIDX];
        float al = rintf((mloc[t] - st) - (128.0f - st));   // exact ref op order
        g_al[ax*NB*NS + b*NS + t] = (int)al;
    }
}

// ========== phase-1 bitmaps (j < K1) + container zeroing ==========
__global__ void k_bitmap1(const float* __restrict__ ev){
    int j = blockIdx.x, b = blockIdx.y, t = threadIdx.x;   // 512 threads
    {
        // zero container: 192 blocks cover 16*65536 ints -> 5462 per block (int4: 1366)
        int blid = b*K1 + j;
        int base = blid * 1366;
        int4 z = make_int4(0,0,0,0);
        for(int i = t; i < 1366; i += 512){
            int idx = base + i;
            if(idx < NB*NPIX/4) ((int4*)g_container)[idx] = z;
        }
    }
    int si = SIDX + j;
    __shared__ unsigned vbm[NVW];
    vbm[t] = 0;
    __syncthreads();
    int ax = g_al[b*NS + si], ay = g_al[NB*NS + b*NS + si];
    const float4* p = reinterpret_cast<const float4*>(
        ev + 2*((size_t)b*(NS*SEGLEN) + (size_t)si*SEGLEN));
    for(int i = t; i < SEGLEN/4; i += 512){
        float4 e0 = p[i];
        float4 e1 = p[i + SEGLEN/4];
        #define VBIT(px, py) { \
            int xs = min(max((int)(px) - ax, 0), 255); \
            int ys = min(max((int)(py) - ay, 0), 255); \
            int iv = (xs >> 1) + ((ys >> 1) << 7); \
            atomicOr(&vbm[iv >> 5], 1u << (iv & 31)); }
        VBIT(e0.x, e0.y) VBIT(e0.z, e0.w)
        VBIT(e1.x, e1.y) VBIT(e1.z, e1.w)
        #undef VBIT
    }
    __syncthreads();
    g_verseg[(size_t)(b*K1 + j)*NVW + t] = vbm[t];
}

// ---- branchless 10-element sort: optimal 29-comparator network ----
#define CSWAP(i,j) { float lo = fminf(v[i], v[j]); float hi = fmaxf(v[i], v[j]); v[i] = lo; v[j] = hi; }
__device__ __forceinline__ void sort10(float* v){
    CSWAP(0,5) CSWAP(1,6) CSWAP(2,7) CSWAP(3,8) CSWAP(4,9)
    CSWAP(0,3) CSWAP(5,8) CSWAP(1,4) CSWAP(6,9)
    CSWAP(0,2) CSWAP(3,6) CSWAP(7,9)
    CSWAP(0,1) CSWAP(2,4) CSWAP(5,7) CSWAP(8,9)
    CSWAP(1,2) CSWAP(3,5) CSWAP(4,6) CSWAP(7,8)
    CSWAP(1,3) CSWAP(2,5) CSWAP(4,7) CSWAP(6,8)
    CSWAP(2,3) CSWAP(4,5) CSWAP(6,7)
    CSWAP(3,4) CSWAP(5,6)
}
#undef CSWAP

// ========== scan: phase-1 from smem stage; phase-2 on demand from events ==========
__global__ void k_scan(const float* __restrict__ ev){
    int b = blockIdx.x, t = threadIdx.x;   // 512 threads == NVW
    int w = t >> 5, lane = t & 31;
    __shared__ unsigned sver[K1][NVW];     // 24KB: phase-1 bitmaps (sver[0] reused as scratch)
    __shared__ unsigned redbuf[16];
    __shared__ unsigned s_tot;
    __shared__ float mm[2][NS];
    __shared__ unsigned char sout[NITER];
    __shared__ int s_done;

    if(t < NS) g_commit[b*NS + t] = 0;
    if(t < 2*NS) ((float*)mm)[t] = g_m[(t/NS)*NB*NS + b*NS + (t%NS)];
    {
        const unsigned* src = g_verseg + (size_t)b*K1*NVW;
        #pragma unroll
        for(int j = 0; j < K1; j++) sver[j][t] = src[j*NVW + t];
    }
    if(t == 0) s_done = 0;
    __syncthreads();

    if(t < NITER){
        bool f = false;
        #pragma unroll
        for(int ax = 0; ax < 2; ax++){
            float w10[10], v[10];
            #pragma unroll
            for(int i = 0; i < 10; i++){ w10[i] = mm[ax][SIDX + 1 + t + i]; v[i] = w10[i]; }
            sort10(v);
            float med = 0.5f*(v[4] + v[5]);
            float d0 = fabsf(w10[0] - med);
            #pragma unroll
            for(int i = 0; i < 10; i++) v[i] = fabsf(w10[i] - med);
            sort10(v);
            float mad = 0.5f*(v[4] + v[5]);
            bool fl = (mad == 0.0f) ? (d0 > 0.0f)
                                    : (__fdiv_rn(0.6745f*d0, mad) > 2.0f);
            f = f || fl;
        }
        sout[t] = f ? 1 : 0;
    }
    __syncthreads();

    unsigned va = sver[0][t];
    unsigned nb = __popc(va);
    #pragma unroll
    for(int o = 16; o; o >>= 1) nb += __shfl_down_sync(0xffffffffu, nb, o);
    if(lane == 0) redbuf[w] = nb;
    __syncthreads();
    if(t == 0){
        unsigned s = 0;
        for(int i = 0; i < 16; i++) s += redbuf[i];
        s_tot = s;
    }
    __syncthreads();
    unsigned cnt = s_tot;
    if(t == 0) g_commit[b*NS + SIDX] = 1;

    // ---- phase 1: smem-staged bitmaps ----
    for(int si = SIDX + 1; si < SIDX + K1; ++si){
        if(sout[si - SIDX - 1]) continue;     // outlier: skip, don't stop
        unsigned wv = sver[si - SIDX][t];
        unsigned nw = __popc(wv & ~va);
        #pragma unroll
        for(int o = 16; o; o >>= 1) nw += __shfl_down_sync(0xffffffffu, nw, o);
        if(lane == 0) redbuf[w] = nw;
        __syncthreads();
        if(t == 0){
            unsigned s = 0;
            for(int i = 0; i < 16; i++) s += redbuf[i];
            s_tot = s;
        }
        __syncthreads();
        unsigned ni = s_tot;
        unsigned cn = cnt + ni;
        if(__fdiv_rn((float)ni, (float)cn) < 0.1f){    // stopped forever
            if(t == 0) s_done = 1;
            break;
        }
        va |= wv;
        cnt = cn;
        if(t == 0) g_commit[b*NS + si] = 1;
        __syncthreads();
    }
    __syncthreads();

    // ---- phase 2 (rare): build remaining bitmaps on demand ----
    if(!s_done){
        const float4* base4 = reinterpret_cast<const float4*>(ev + 2*(size_t)b*(NS*SEGLEN));
        for(int si = SIDX + K1; si < EIDX; ++si){
            if(sout[si - SIDX - 1]) continue;
            sver[0][t] = 0;
            __syncthreads();
            int ax = g_al[b*NS + si], ay = g_al[NB*NS + b*NS + si];
            const float4* p = base4 + (size_t)si*(SEGLEN/2);
            for(int i = t; i < SEGLEN/4; i += 512){
                float4 e0 = p[i];
                float4 e1 = p[i + SEGLEN/4];
                #define VBIT(px, py) { \
                    int xs = min(max((int)(px) - ax, 0), 255); \
                    int ys = min(max((int)(py) - ay, 0), 255); \
                    int iv = (xs >> 1) + ((ys >> 1) << 7); \
                    atomicOr(&sver[0][iv >> 5], 1u << (iv & 31)); }
                VBIT(e0.x, e0.y) VBIT(e0.z, e0.w)
                VBIT(e1.x, e1.y) VBIT(e1.z, e1.w)
                #undef VBIT
            }
            __syncthreads();
            unsigned wv = sver[0][t];
            unsigned nw = __popc(wv & ~va);
            #pragma unroll
            for(int o = 16; o; o >>= 1) nw += __shfl_down_sync(0xffffffffu, nw, o);
            if(lane == 0) redbuf[w] = nw;
            __syncthreads();
            if(t == 0){
                unsigned s = 0;
                for(int i = 0; i < 16; i++) s += redbuf[i];
                s_tot = s;
            }
            __syncthreads();
            unsigned ni = s_tot;
            unsigned cn = cnt + ni;
            if(__fdiv_rn((float)ni, (float)cn) < 0.1f) break;
            va |= wv;
            cnt = cn;
            if(t == 0) g_commit[b*NS + si] = 1;
            __syncthreads();
        }
    }
}

// ================= container scatter for committed segments =================
__global__ void k_scatter(const float* __restrict__ ev){
    int si = SIDX + blockIdx.x, b = blockIdx.y, ck = blockIdx.z;   // z: 8 chunks
    if(!g_commit[b*NS + si]) return;
    int ax = g_al[b*NS + si], ay = g_al[NB*NS + b*NS + si];
    const float4* p = reinterpret_cast<const float4*>(
        ev + 2*((size_t)b*(NS*SEGLEN) + (size_t)si*SEGLEN));
    int* cont = g_container + b*NPIX;
    int lo = ck * (SEGLEN/16), hi = lo + (SEGLEN/16);
    for(int i = lo + threadIdx.x; i < hi; i += blockDim.x){
        float4 e = p[i];
        {
            int xs = min(max((int)e.x - ax, 0), 255);
            int ys = min(max((int)e.y - ay, 0), 255);
            atomicAdd(&cont[xs + (ys << 8)], 1);
        }
        {
            int xs = min(max((int)e.z - ax, 0), 255);
            int ys = min(max((int)e.w - ay, 0), 255);
            atomicAdd(&cont[xs + (ys << 8)], 1);
        }
    }
}

// ========== final: single-pass stats + normalize (device-side sync) ==========
// grid (16, NB) = 256 blocks, all co-resident (256 < 592 slots) -> spin is safe
__global__ void k_final(float* __restrict__ out){
    int pb = blockIdx.x, b = blockIdx.y, t = threadIdx.x;   // 512 threads
    const int* c = g_container + b*NPIX + pb*4096;
    int vals[8];
    ull s1 = 0, s2 = 0;
    #pragma unroll
    for(int k = 0; k < 8; k++){
        int v = c[t + 512*k];
        vals[k] = v;
        s1 += (unsigned)v;
        s2 += (ull)(unsigned)v * (unsigned)v;
    }
    __shared__ ull a1[512], a2[512];
    __shared__ float scv;
    a1[t] = s1; a2[t] = s2; __syncthreads();
    for(int o = 256; o; o >>= 1){
        if(t < o){ a1[t] += a1[t+o]; a2[t] += a2[t+o]; }
        __syncthreads();
    }
    if(t == 0){
        atomicAdd(&g_acc[b][0], a1[0]);
        atomicAdd(&g_acc[b][1], a2[0]);
        __threadfence();
        unsigned done = atomicAdd(&g_fcount, 1u) + 1;
        while(done < NFB){
            __nanosleep(64);
            done = atomicAdd(&g_fcount, 0u);
        }
        __threadfence();
        double n = (double)NPIX;
        double t1 = (double)atomicAdd(&g_acc[b][0], 0ULL);
        double t2 = (double)atomicAdd(&g_acc[b][1], 0ULL);
        double mean = t1 / n;
        double var  = (t2 - t1*t1/n) / (n - 1.0);
        scv = (float)(mean + 3.0*sqrt(var));
    }
    __syncthreads();
    float cv = scv;
    float* o = out + b*NPIX + pb*4096;
    #pragma unroll
    for(int k = 0; k < 8; k++){
        float v = fminf((float)vals[k], cv);
        o[t + 512*k] = __fdiv_rn(v, cv);
    }
}

// ================= launch =================
extern "C" void kernel_launch(void* const* d_in, const int* in_sizes, int n_in,
                              void* d_out, int out_size){
    const float* ev = (const float*)d_in[0];
    float* out = (float*)d_out;
    (void)in_sizes; (void)n_in; (void)out_size;

    { dim3 g(NS, NB);      k_hist   <<<g, HT>>>(ev); }
    { dim3 g(NB, 2);       k_stats  <<<g, 512>>>(); }
    { dim3 g(K1, NB);      k_bitmap1<<<g, 512>>>(ev); }
    k_scan<<<NB, NVW>>>(ev);                              // profile slot #4 (canary)
    { dim3 g(NSEG, NB, 8); k_scatter<<<g, 512>>>(ev); }
    { dim3 g(16, NB);      k_final  <<<g, 512>>>(out); }
}